// round 3
// baseline (speedup 1.0000x reference)
#include <cuda_runtime.h>
#include <cstdint>

#define NTOK 16384
#define HID  4096
#define RANK 8
#define LSCALE 1.0f   /* ALPHA / RANK = 8/8 */

#define BM 128
#define BN 128
#define BK 16
#define PAD 20        /* smem row stride (floats): conflict-free for frag loads, 16B aligned */

__device__ float g_z[NTOK * RANK];
__device__ int   g_e[NTOK];

__device__ __forceinline__ float warp_sum(float v) {
#pragma unroll
    for (int o = 16; o > 0; o >>= 1) v += __shfl_xor_sync(0xffffffffu, v, o);
    return v;
}

__device__ __forceinline__ unsigned f2tf(float f) {
    unsigned u;
    asm("cvt.rna.tf32.f32 %0, %1;" : "=r"(u) : "f"(f));
    return u;
}

__device__ __forceinline__ float dot4(float4 a, float4 b) {
    return a.x * b.x + a.y * b.y + a.z * b.z + a.w * b.w;
}

// ---------------------------------------------------------------------------
// Kernel A: routing (fp32-exact logits -> argmax) + z = x @ lora_A[e]^T
// warp per token; 128 threads / block; 4 tokens / block
// ---------------------------------------------------------------------------
__global__ __launch_bounds__(128) void route_kernel(
    const float* __restrict__ x, const float* __restrict__ gate_w,
    const float* __restrict__ bias, const float* __restrict__ lora_A)
{
    const int warp = threadIdx.x >> 5;
    const int lane = threadIdx.x & 31;
    const int n = blockIdx.x * 4 + warp;
    const float* xr = x + (size_t)n * HID;

    // Phase 1: 4 logits in fp32 (argmax must be exact-ish)
    float a0 = 0.f, a1 = 0.f, a2 = 0.f, a3 = 0.f;
#pragma unroll 4
    for (int it = 0; it < HID / 128; ++it) {
        int h = (it * 32 + lane) * 4;
        float4 xv = *reinterpret_cast<const float4*>(xr + h);
        a0 += dot4(xv, *reinterpret_cast<const float4*>(gate_w + 0 * HID + h));
        a1 += dot4(xv, *reinterpret_cast<const float4*>(gate_w + 1 * HID + h));
        a2 += dot4(xv, *reinterpret_cast<const float4*>(gate_w + 2 * HID + h));
        a3 += dot4(xv, *reinterpret_cast<const float4*>(gate_w + 3 * HID + h));
    }
    a0 = warp_sum(a0) + bias[0];
    a1 = warp_sum(a1) + bias[1];
    a2 = warp_sum(a2) + bias[2];
    a3 = warp_sum(a3) + bias[3];
    // argmax, first-max wins (matches jnp.argmax) — identical on all lanes
    int best = 0; float bv = a0;
    if (a1 > bv) { bv = a1; best = 1; }
    if (a2 > bv) { bv = a2; best = 2; }
    if (a3 > bv) { bv = a3; best = 3; }

    // Phase 2: z[r] = <x, lora_A[best, r, :]>
    const float* Ab = lora_A + (size_t)best * RANK * HID;
    float z[RANK];
#pragma unroll
    for (int r = 0; r < RANK; ++r) z[r] = 0.f;
#pragma unroll 2
    for (int it = 0; it < HID / 128; ++it) {
        int h = (it * 32 + lane) * 4;
        float4 xv = *reinterpret_cast<const float4*>(xr + h);
#pragma unroll
        for (int r = 0; r < RANK; ++r)
            z[r] += dot4(xv, *reinterpret_cast<const float4*>(Ab + r * HID + h));
    }
#pragma unroll
    for (int r = 0; r < RANK; ++r) z[r] = warp_sum(z[r]);

    if (lane == 0) {
        g_e[n] = best;
#pragma unroll
        for (int r = 0; r < RANK; ++r)
            g_z[(size_t)n * RANK + r] = z[r] * LSCALE;
    }
}

// ---------------------------------------------------------------------------
// Kernel B: out = x @ W_up^T + LoRA delta (fused epilogue)
// tf32 mma.sync m16n8k8, 128x128x16 tiles, double-buffered smem,
// 8 warps (2 x 4), warp tile 64x32 (4 x 4 mma tiles)
// ---------------------------------------------------------------------------
__device__ __forceinline__ void mma8(float* c, const unsigned* a, const unsigned* b) {
    asm volatile(
        "mma.sync.aligned.m16n8k8.row.col.f32.tf32.tf32.f32 "
        "{%0,%1,%2,%3},{%4,%5,%6,%7},{%8,%9},{%0,%1,%2,%3};"
        : "+f"(c[0]), "+f"(c[1]), "+f"(c[2]), "+f"(c[3])
        : "r"(a[0]), "r"(a[1]), "r"(a[2]), "r"(a[3]), "r"(b[0]), "r"(b[1]));
}

__global__ __launch_bounds__(256, 2) void gemm_lora_kernel(
    const float* __restrict__ X, const float* __restrict__ W,
    const float* __restrict__ loraB, float* __restrict__ out)
{
    __shared__ float smem[4 * BM * PAD];   // A[2] then B[2]; 40 KB

    const int tid  = threadIdx.x;
    const int wid  = tid >> 5, lane = tid & 31;
    const int wm   = wid & 1,  wn   = wid >> 1;
    const int g    = lane >> 2, tc  = lane & 3;
    const int m0   = blockIdx.y * BM, n0 = blockIdx.x * BN;

    float acc[4][4][4];
#pragma unroll
    for (int i = 0; i < 4; ++i)
#pragma unroll
        for (int j = 0; j < 4; ++j)
#pragma unroll
            for (int k = 0; k < 4; ++k) acc[i][j][k] = 0.f;

    // global->smem staging indices: thread loads rows (lrow, lrow+64), 4 floats at lcol
    const int lrow = tid >> 2;
    const int lcol = (tid & 3) * 4;
    const float* Xp = X + (size_t)(m0 + lrow) * HID + lcol;
    const float* Wp = W + (size_t)(n0 + lrow) * HID + lcol;

    // prologue: tile 0
    {
        float4 a0 = *reinterpret_cast<const float4*>(Xp);
        float4 a1 = *reinterpret_cast<const float4*>(Xp + (size_t)64 * HID);
        float4 b0 = *reinterpret_cast<const float4*>(Wp);
        float4 b1 = *reinterpret_cast<const float4*>(Wp + (size_t)64 * HID);
        float* A = smem;
        float* B = smem + 2 * BM * PAD;
        A[lrow * PAD + lcol + 0] = __uint_as_float(f2tf(a0.x));
        A[lrow * PAD + lcol + 1] = __uint_as_float(f2tf(a0.y));
        A[lrow * PAD + lcol + 2] = __uint_as_float(f2tf(a0.z));
        A[lrow * PAD + lcol + 3] = __uint_as_float(f2tf(a0.w));
        A[(lrow + 64) * PAD + lcol + 0] = __uint_as_float(f2tf(a1.x));
        A[(lrow + 64) * PAD + lcol + 1] = __uint_as_float(f2tf(a1.y));
        A[(lrow + 64) * PAD + lcol + 2] = __uint_as_float(f2tf(a1.z));
        A[(lrow + 64) * PAD + lcol + 3] = __uint_as_float(f2tf(a1.w));
        B[lrow * PAD + lcol + 0] = __uint_as_float(f2tf(b0.x));
        B[lrow * PAD + lcol + 1] = __uint_as_float(f2tf(b0.y));
        B[lrow * PAD + lcol + 2] = __uint_as_float(f2tf(b0.z));
        B[lrow * PAD + lcol + 3] = __uint_as_float(f2tf(b0.w));
        B[(lrow + 64) * PAD + lcol + 0] = __uint_as_float(f2tf(b1.x));
        B[(lrow + 64) * PAD + lcol + 1] = __uint_as_float(f2tf(b1.y));
        B[(lrow + 64) * PAD + lcol + 2] = __uint_as_float(f2tf(b1.z));
        B[(lrow + 64) * PAD + lcol + 3] = __uint_as_float(f2tf(b1.w));
    }
    __syncthreads();

    const int nk = HID / BK;   // 256
    for (int kt = 0; kt < nk; ++kt) {
        const int cur = kt & 1;

        // issue next tile's global loads early (overlap with mma)
        float4 na0, na1, nb0, nb1;
        if (kt + 1 < nk) {
            const int off = (kt + 1) * BK;
            na0 = *reinterpret_cast<const float4*>(Xp + off);
            na1 = *reinterpret_cast<const float4*>(Xp + (size_t)64 * HID + off);
            nb0 = *reinterpret_cast<const float4*>(Wp + off);
            nb1 = *reinterpret_cast<const float4*>(Wp + (size_t)64 * HID + off);
        }

        const float* A = smem + cur * BM * PAD;
        const float* B = smem + (2 + cur) * BM * PAD;
#pragma unroll
        for (int ks = 0; ks < 2; ++ks) {
            const int k0 = ks * 8;
            unsigned af[4][4], bf[4][2];
#pragma unroll
            for (int mi = 0; mi < 4; ++mi) {
                const int rb = wm * 64 + mi * 16;
                af[mi][0] = __float_as_uint(A[(rb + g) * PAD + k0 + tc]);
                af[mi][1] = __float_as_uint(A[(rb + g + 8) * PAD + k0 + tc]);
                af[mi][2] = __float_as_uint(A[(rb + g) * PAD + k0 + tc + 4]);
                af[mi][3] = __float_as_uint(A[(rb + g + 8) * PAD + k0 + tc + 4]);
            }
#pragma unroll
            for (int nj = 0; nj < 4; ++nj) {
                const int cb = wn * 32 + nj * 8;
                bf[nj][0] = __float_as_uint(B[(cb + g) * PAD + k0 + tc]);
                bf[nj][1] = __float_as_uint(B[(cb + g) * PAD + k0 + tc + 4]);
            }
#pragma unroll
            for (int mi = 0; mi < 4; ++mi)
#pragma unroll
                for (int nj = 0; nj < 4; ++nj)
                    mma8(acc[mi][nj], af[mi], bf[nj]);
        }

        if (kt + 1 < nk) {
            float* An = smem + (1 - cur) * BM * PAD;
            float* Bn = smem + (2 + (1 - cur)) * BM * PAD;
            An[lrow * PAD + lcol + 0] = __uint_as_float(f2tf(na0.x));
            An[lrow * PAD + lcol + 1] = __uint_as_float(f2tf(na0.y));
            An[lrow * PAD + lcol + 2] = __uint_as_float(f2tf(na0.z));
            An[lrow * PAD + lcol + 3] = __uint_as_float(f2tf(na0.w));
            An[(lrow + 64) * PAD + lcol + 0] = __uint_as_float(f2tf(na1.x));
            An[(lrow + 64) * PAD + lcol + 1] = __uint_as_float(f2tf(na1.y));
            An[(lrow + 64) * PAD + lcol + 2] = __uint_as_float(f2tf(na1.z));
            An[(lrow + 64) * PAD + lcol + 3] = __uint_as_float(f2tf(na1.w));
            Bn[lrow * PAD + lcol + 0] = __uint_as_float(f2tf(nb0.x));
            Bn[lrow * PAD + lcol + 1] = __uint_as_float(f2tf(nb0.y));
            Bn[lrow * PAD + lcol + 2] = __uint_as_float(f2tf(nb0.z));
            Bn[lrow * PAD + lcol + 3] = __uint_as_float(f2tf(nb0.w));
            Bn[(lrow + 64) * PAD + lcol + 0] = __uint_as_float(f2tf(nb1.x));
            Bn[(lrow + 64) * PAD + lcol + 1] = __uint_as_float(f2tf(nb1.y));
            Bn[(lrow + 64) * PAD + lcol + 2] = __uint_as_float(f2tf(nb1.z));
            Bn[(lrow + 64) * PAD + lcol + 3] = __uint_as_float(f2tf(nb1.w));
        }
        __syncthreads();
    }

    // ---------------- epilogue: fuse LoRA delta ----------------
    // repurpose smem: zs[128*8] | es[128] | Bl[4][128][8]
    float* zs = smem;
    int*   es = reinterpret_cast<int*>(smem + 1024);
    float* Bl = smem + 1152;

    reinterpret_cast<float4*>(zs)[tid] =
        reinterpret_cast<const float4*>(g_z + (size_t)m0 * RANK)[tid];
    if (tid < BM) es[tid] = g_e[m0 + tid];
#pragma unroll
    for (int i = tid; i < 1024; i += 256) {
        const int e = i >> 8, j = i & 255;
        reinterpret_cast<float4*>(Bl)[i] =
            reinterpret_cast<const float4*>(loraB + ((size_t)e * HID + n0) * RANK)[j];
    }
    __syncthreads();

#pragma unroll
    for (int mi = 0; mi < 4; ++mi) {
#pragma unroll
        for (int rp = 0; rp < 2; ++rp) {
            const int row = wm * 64 + mi * 16 + rp * 8 + g;
            const int e = es[row];
            const float4 z0 = *reinterpret_cast<const float4*>(zs + row * 8);
            const float4 z1 = *reinterpret_cast<const float4*>(zs + row * 8 + 4);
            float* orow = out + (size_t)(m0 + row) * HID + n0;
            const float* Be = Bl + e * 1024;
#pragma unroll
            for (int nj = 0; nj < 4; ++nj) {
                const int cl = wn * 32 + nj * 8 + tc * 2;
                float v[2];
#pragma unroll
                for (int cc = 0; cc < 2; ++cc) {
                    const float4 bA = *reinterpret_cast<const float4*>(Be + (cl + cc) * 8);
                    const float4 bB = *reinterpret_cast<const float4*>(Be + (cl + cc) * 8 + 4);
                    const float d = dot4(z0, bA) + dot4(z1, bB);
                    v[cc] = acc[mi][nj][rp * 2 + cc] + d;
                }
                float2 st; st.x = v[0]; st.y = v[1];
                *reinterpret_cast<float2*>(orow + cl) = st;
            }
        }
    }
}

// ---------------------------------------------------------------------------
extern "C" void kernel_launch(void* const* d_in, const int* in_sizes, int n_in,
                              void* d_out, int out_size)
{
    const float* x    = (const float*)d_in[0];
    const float* W    = (const float*)d_in[1];
    const float* gate = (const float*)d_in[2];
    const float* bias = (const float*)d_in[3];
    const float* lA   = (const float*)d_in[4];
    const float* lB   = (const float*)d_in[5];
    float* out = (float*)d_out;
    (void)in_sizes; (void)n_in; (void)out_size;

    route_kernel<<<NTOK / 4, 128>>>(x, gate, bias, lA);
    dim3 grid(HID / BN, NTOK / BM);
    gemm_lora_kernel<<<grid, 256>>>(x, W, lB, out);
}

// round 5
// speedup vs baseline: 1.0016x; 1.0016x over previous
#include <cuda_runtime.h>
#include <cstdint>

#define NTOK 16384
#define HID  4096
#define RANK 8
#define LSCALE 1.0f   /* ALPHA / RANK = 8/8 */

#define BM 128
#define BN 128
#define BK 16
#define PAD 20        /* smem row stride (floats): conflict-free for frag loads, 16B aligned */

__device__ float g_z[NTOK * RANK];
__device__ int   g_e[NTOK];

__device__ __forceinline__ float warp_sum(float v) {
#pragma unroll
    for (int o = 16; o > 0; o >>= 1) v += __shfl_xor_sync(0xffffffffu, v, o);
    return v;
}

__device__ __forceinline__ unsigned f2tf(float f) {
    unsigned u;
    asm("cvt.rna.tf32.f32 %0, %1;" : "=r"(u) : "f"(f));
    return u;
}

__device__ __forceinline__ float dot4(float4 a, float4 b) {
    return a.x * b.x + a.y * b.y + a.z * b.z + a.w * b.w;
}

// ---------------------------------------------------------------------------
// Kernel A: routing (fp32-exact logits -> argmax) + z = x @ lora_A[e]^T
// warp per token; 128 threads / block; 4 tokens / block
// ---------------------------------------------------------------------------
__global__ __launch_bounds__(128) void route_kernel(
    const float* __restrict__ x, const float* __restrict__ gate_w,
    const float* __restrict__ bias, const float* __restrict__ lora_A)
{
    const int warp = threadIdx.x >> 5;
    const int lane = threadIdx.x & 31;
    const int n = blockIdx.x * 4 + warp;
    const float* xr = x + (size_t)n * HID;

    // Phase 1: 4 logits in fp32 (argmax must be exact-ish)
    float a0 = 0.f, a1 = 0.f, a2 = 0.f, a3 = 0.f;
#pragma unroll 4
    for (int it = 0; it < HID / 128; ++it) {
        int h = (it * 32 + lane) * 4;
        float4 xv = *reinterpret_cast<const float4*>(xr + h);
        a0 += dot4(xv, *reinterpret_cast<const float4*>(gate_w + 0 * HID + h));
        a1 += dot4(xv, *reinterpret_cast<const float4*>(gate_w + 1 * HID + h));
        a2 += dot4(xv, *reinterpret_cast<const float4*>(gate_w + 2 * HID + h));
        a3 += dot4(xv, *reinterpret_cast<const float4*>(gate_w + 3 * HID + h));
    }
    a0 = warp_sum(a0) + bias[0];
    a1 = warp_sum(a1) + bias[1];
    a2 = warp_sum(a2) + bias[2];
    a3 = warp_sum(a3) + bias[3];
    // argmax, first-max wins (matches jnp.argmax) — identical on all lanes
    int best = 0; float bv = a0;
    if (a1 > bv) { bv = a1; best = 1; }
    if (a2 > bv) { bv = a2; best = 2; }
    if (a3 > bv) { bv = a3; best = 3; }

    // Phase 2: z[r] = <x, lora_A[best, r, :]>
    const float* Ab = lora_A + (size_t)best * RANK * HID;
    float z[RANK];
#pragma unroll
    for (int r = 0; r < RANK; ++r) z[r] = 0.f;
#pragma unroll 2
    for (int it = 0; it < HID / 128; ++it) {
        int h = (it * 32 + lane) * 4;
        float4 xv = *reinterpret_cast<const float4*>(xr + h);
#pragma unroll
        for (int r = 0; r < RANK; ++r)
            z[r] += dot4(xv, *reinterpret_cast<const float4*>(Ab + r * HID + h));
    }
#pragma unroll
    for (int r = 0; r < RANK; ++r) z[r] = warp_sum(z[r]);

    if (lane == 0) {
        g_e[n] = best;
#pragma unroll
        for (int r = 0; r < RANK; ++r)
            g_z[(size_t)n * RANK + r] = z[r] * LSCALE;
    }
}

// ---------------------------------------------------------------------------
// Kernel B: out = x @ W_up^T + LoRA delta (fused epilogue)
// tf32 mma.sync m16n8k8, 128x128x16 tiles, double-buffered smem,
// 8 warps (2 x 4), warp tile 64x32 (4 x 4 mma tiles)
// ---------------------------------------------------------------------------
__device__ __forceinline__ void mma8(float* c, const unsigned* a, const unsigned* b) {
    asm volatile(
        "mma.sync.aligned.m16n8k8.row.col.f32.tf32.tf32.f32 "
        "{%0,%1,%2,%3},{%4,%5,%6,%7},{%8,%9},{%0,%1,%2,%3};"
        : "+f"(c[0]), "+f"(c[1]), "+f"(c[2]), "+f"(c[3])
        : "r"(a[0]), "r"(a[1]), "r"(a[2]), "r"(a[3]), "r"(b[0]), "r"(b[1]));
}

__global__ __launch_bounds__(256, 2) void gemm_lora_kernel(
    const float* __restrict__ X, const float* __restrict__ W,
    const float* __restrict__ loraB, float* __restrict__ out)
{
    __shared__ float smem[4 * BM * PAD];   // A[2] then B[2]; 40 KB

    const int tid  = threadIdx.x;
    const int wid  = tid >> 5, lane = tid & 31;
    const int wm   = wid & 1,  wn   = wid >> 1;
    const int g    = lane >> 2, tc  = lane & 3;
    const int m0   = blockIdx.y * BM, n0 = blockIdx.x * BN;

    float acc[4][4][4];
#pragma unroll
    for (int i = 0; i < 4; ++i)
#pragma unroll
        for (int j = 0; j < 4; ++j)
#pragma unroll
            for (int k = 0; k < 4; ++k) acc[i][j][k] = 0.f;

    // global->smem staging indices: thread loads rows (lrow, lrow+64), 4 floats at lcol
    const int lrow = tid >> 2;
    const int lcol = (tid & 3) * 4;
    const float* Xp = X + (size_t)(m0 + lrow) * HID + lcol;
    const float* Wp = W + (size_t)(n0 + lrow) * HID + lcol;

    // prologue: tile 0
    {
        float4 a0 = *reinterpret_cast<const float4*>(Xp);
        float4 a1 = *reinterpret_cast<const float4*>(Xp + (size_t)64 * HID);
        float4 b0 = *reinterpret_cast<const float4*>(Wp);
        float4 b1 = *reinterpret_cast<const float4*>(Wp + (size_t)64 * HID);
        float* A = smem;
        float* B = smem + 2 * BM * PAD;
        A[lrow * PAD + lcol + 0] = __uint_as_float(f2tf(a0.x));
        A[lrow * PAD + lcol + 1] = __uint_as_float(f2tf(a0.y));
        A[lrow * PAD + lcol + 2] = __uint_as_float(f2tf(a0.z));
        A[lrow * PAD + lcol + 3] = __uint_as_float(f2tf(a0.w));
        A[(lrow + 64) * PAD + lcol + 0] = __uint_as_float(f2tf(a1.x));
        A[(lrow + 64) * PAD + lcol + 1] = __uint_as_float(f2tf(a1.y));
        A[(lrow + 64) * PAD + lcol + 2] = __uint_as_float(f2tf(a1.z));
        A[(lrow + 64) * PAD + lcol + 3] = __uint_as_float(f2tf(a1.w));
        B[lrow * PAD + lcol + 0] = __uint_as_float(f2tf(b0.x));
        B[lrow * PAD + lcol + 1] = __uint_as_float(f2tf(b0.y));
        B[lrow * PAD + lcol + 2] = __uint_as_float(f2tf(b0.z));
        B[lrow * PAD + lcol + 3] = __uint_as_float(f2tf(b0.w));
        B[(lrow + 64) * PAD + lcol + 0] = __uint_as_float(f2tf(b1.x));
        B[(lrow + 64) * PAD + lcol + 1] = __uint_as_float(f2tf(b1.y));
        B[(lrow + 64) * PAD + lcol + 2] = __uint_as_float(f2tf(b1.z));
        B[(lrow + 64) * PAD + lcol + 3] = __uint_as_float(f2tf(b1.w));
    }
    __syncthreads();

    const int nk = HID / BK;   // 256
    for (int kt = 0; kt < nk; ++kt) {
        const int cur = kt & 1;

        // issue next tile's global loads early (overlap with mma)
        float4 na0, na1, nb0, nb1;
        if (kt + 1 < nk) {
            const int off = (kt + 1) * BK;
            na0 = *reinterpret_cast<const float4*>(Xp + off);
            na1 = *reinterpret_cast<const float4*>(Xp + (size_t)64 * HID + off);
            nb0 = *reinterpret_cast<const float4*>(Wp + off);
            nb1 = *reinterpret_cast<const float4*>(Wp + (size_t)64 * HID + off);
        }

        const float* A = smem + cur * BM * PAD;
        const float* B = smem + (2 + cur) * BM * PAD;
#pragma unroll
        for (int ks = 0; ks < 2; ++ks) {
            const int k0 = ks * 8;
            unsigned af[4][4], bf[4][2];
#pragma unroll
            for (int mi = 0; mi < 4; ++mi) {
                const int rb = wm * 64 + mi * 16;
                af[mi][0] = __float_as_uint(A[(rb + g) * PAD + k0 + tc]);
                af[mi][1] = __float_as_uint(A[(rb + g + 8) * PAD + k0 + tc]);
                af[mi][2] = __float_as_uint(A[(rb + g) * PAD + k0 + tc + 4]);
                af[mi][3] = __float_as_uint(A[(rb + g + 8) * PAD + k0 + tc + 4]);
            }
#pragma unroll
            for (int nj = 0; nj < 4; ++nj) {
                const int cb = wn * 32 + nj * 8;
                bf[nj][0] = __float_as_uint(B[(cb + g) * PAD + k0 + tc]);
                bf[nj][1] = __float_as_uint(B[(cb + g) * PAD + k0 + tc + 4]);
            }
#pragma unroll
            for (int mi = 0; mi < 4; ++mi)
#pragma unroll
                for (int nj = 0; nj < 4; ++nj)
                    mma8(acc[mi][nj], af[mi], bf[nj]);
        }

        if (kt + 1 < nk) {
            float* An = smem + (1 - cur) * BM * PAD;
            float* Bn = smem + (2 + (1 - cur)) * BM * PAD;
            An[lrow * PAD + lcol + 0] = __uint_as_float(f2tf(na0.x));
            An[lrow * PAD + lcol + 1] = __uint_as_float(f2tf(na0.y));
            An[lrow * PAD + lcol + 2] = __uint_as_float(f2tf(na0.z));
            An[lrow * PAD + lcol + 3] = __uint_as_float(f2tf(na0.w));
            An[(lrow + 64) * PAD + lcol + 0] = __uint_as_float(f2tf(na1.x));
            An[(lrow + 64) * PAD + lcol + 1] = __uint_as_float(f2tf(na1.y));
            An[(lrow + 64) * PAD + lcol + 2] = __uint_as_float(f2tf(na1.z));
            An[(lrow + 64) * PAD + lcol + 3] = __uint_as_float(f2tf(na1.w));
            Bn[lrow * PAD + lcol + 0] = __uint_as_float(f2tf(nb0.x));
            Bn[lrow * PAD + lcol + 1] = __uint_as_float(f2tf(nb0.y));
            Bn[lrow * PAD + lcol + 2] = __uint_as_float(f2tf(nb0.z));
            Bn[lrow * PAD + lcol + 3] = __uint_as_float(f2tf(nb0.w));
            Bn[(lrow + 64) * PAD + lcol + 0] = __uint_as_float(f2tf(nb1.x));
            Bn[(lrow + 64) * PAD + lcol + 1] = __uint_as_float(f2tf(nb1.y));
            Bn[(lrow + 64) * PAD + lcol + 2] = __uint_as_float(f2tf(nb1.z));
            Bn[(lrow + 64) * PAD + lcol + 3] = __uint_as_float(f2tf(nb1.w));
        }
        __syncthreads();
    }

    // ---------------- epilogue: fuse LoRA delta ----------------
    // repurpose smem: zs[128*8] | es[128] | Bl[4][128][8]
    float* zs = smem;
    int*   es = reinterpret_cast<int*>(smem + 1024);
    float* Bl = smem + 1152;

    reinterpret_cast<float4*>(zs)[tid] =
        reinterpret_cast<const float4*>(g_z + (size_t)m0 * RANK)[tid];
    if (tid < BM) es[tid] = g_e[m0 + tid];
#pragma unroll
    for (int i = tid; i < 1024; i += 256) {
        const int e = i >> 8, j = i & 255;
        reinterpret_cast<float4*>(Bl)[i] =
            reinterpret_cast<const float4*>(loraB + ((size_t)e * HID + n0) * RANK)[j];
    }
    __syncthreads();

#pragma unroll
    for (int mi = 0; mi < 4; ++mi) {
#pragma unroll
        for (int rp = 0; rp < 2; ++rp) {
            const int row = wm * 64 + mi * 16 + rp * 8 + g;
            const int e = es[row];
            const float4 z0 = *reinterpret_cast<const float4*>(zs + row * 8);
            const float4 z1 = *reinterpret_cast<const float4*>(zs + row * 8 + 4);
            float* orow = out + (size_t)(m0 + row) * HID + n0;
            const float* Be = Bl + e * 1024;
#pragma unroll
            for (int nj = 0; nj < 4; ++nj) {
                const int cl = wn * 32 + nj * 8 + tc * 2;
                float v[2];
#pragma unroll
                for (int cc = 0; cc < 2; ++cc) {
                    const float4 bA = *reinterpret_cast<const float4*>(Be + (cl + cc) * 8);
                    const float4 bB = *reinterpret_cast<const float4*>(Be + (cl + cc) * 8 + 4);
                    const float d = dot4(z0, bA) + dot4(z1, bB);
                    v[cc] = acc[mi][nj][rp * 2 + cc] + d;
                }
                float2 st; st.x = v[0]; st.y = v[1];
                *reinterpret_cast<float2*>(orow + cl) = st;
            }
        }
    }
}

// ---------------------------------------------------------------------------
extern "C" void kernel_launch(void* const* d_in, const int* in_sizes, int n_in,
                              void* d_out, int out_size)
{
    const float* x    = (const float*)d_in[0];
    const float* W    = (const float*)d_in[1];
    const float* gate = (const float*)d_in[2];
    const float* bias = (const float*)d_in[3];
    const float* lA   = (const float*)d_in[4];
    const float* lB   = (const float*)d_in[5];
    float* out = (float*)d_out;
    (void)in_sizes; (void)n_in; (void)out_size;

    route_kernel<<<NTOK / 4, 128>>>(x, gate, bias, lA);
    dim3 grid(HID / BN, NTOK / BM);
    gemm_lora_kernel<<<grid, 256>>>(x, W, lB, out);
}

// round 7
// speedup vs baseline: 1.4289x; 1.4266x over previous
#include <cuda_runtime.h>
#include <cstdint>

#define NTOK 16384
#define HID  4096
#define RANK 8

// ---- GEMM tiling ----
#define BM 128
#define BN 256
#define BK 32
#define NKI (HID / BK)            /* 128 k-iterations */
#define A_STAGE 16384             /* 128*32*4 bytes */
#define B_STAGE 32768             /* 256*32*4 bytes */
#define STAGE   (A_STAGE + B_STAGE)   /* 49152 */
#define NSTAGE 3
#define SMEM_DYN (NSTAGE * STAGE)     /* 147456 */

// ---- fragment-ordered packed operands ----
// X: [mt(128)][ktile(256)] tiles of 128x16; tile = 16 subs(mb*2+ks) x 32 lanes x float4
__device__ float4 g_Xp[(size_t)NTOK * HID / 4];
// W: [nt(16)][ktile(256)] tiles of 256x16; tile = 64 subs(nb*2+ks) x 32 lanes x float2
__device__ float2 g_Wp[(size_t)HID * HID / 2];
__device__ float g_z[NTOK * RANK];
__device__ int   g_e[NTOK];

// ======================= helpers =======================
__device__ __forceinline__ uint32_t smem_u32(const void* p) {
    uint32_t a;
    asm("{ .reg .u64 t; cvta.to.shared.u64 t, %1; cvt.u32.u64 %0, t; }" : "=r"(a) : "l"(p));
    return a;
}
__device__ __forceinline__ float rna_tf32(float f) {
    unsigned u;
    asm("cvt.rna.tf32.f32 %0, %1;" : "=r"(u) : "f"(f));
    return __uint_as_float(u);
}
__device__ __forceinline__ float warp_sum(float v) {
#pragma unroll
    for (int o = 16; o > 0; o >>= 1) v += __shfl_xor_sync(0xffffffffu, v, o);
    return v;
}
__device__ __forceinline__ float dot4(float4 a, float4 b) {
    return a.x * b.x + a.y * b.y + a.z * b.z + a.w * b.w;
}
__device__ __forceinline__ void mma8(float* c, const unsigned* a, const unsigned* b) {
    asm volatile(
        "mma.sync.aligned.m16n8k8.row.col.f32.tf32.tf32.f32 "
        "{%0,%1,%2,%3},{%4,%5,%6,%7},{%8,%9},{%0,%1,%2,%3};"
        : "+f"(c[0]), "+f"(c[1]), "+f"(c[2]), "+f"(c[3])
        : "r"(a[0]), "r"(a[1]), "r"(a[2]), "r"(a[3]), "r"(b[0]), "r"(b[1]));
}
#define CP_ASYNC16(dst, src) \
    asm volatile("cp.async.cg.shared.global [%0], [%1], 16;" :: "r"(dst), "l"(src) : "memory")
#define CP_COMMIT() asm volatile("cp.async.commit_group;" ::: "memory")
#define CP_WAIT1()  asm volatile("cp.async.wait_group 1;" ::: "memory")
#define CP_WAIT0()  asm volatile("cp.async.wait_group 0;" ::: "memory")
#define LDS128(r, a)                                                        \
    asm volatile("ld.shared.v4.b32 {%0,%1,%2,%3}, [%4];"                    \
        : "=r"((r)[0]), "=r"((r)[1]), "=r"((r)[2]), "=r"((r)[3]) : "r"(a))
#define LDS64(r, a)                                                         \
    asm volatile("ld.shared.v2.b32 {%0,%1}, [%2];"                          \
        : "=r"((r)[0]), "=r"((r)[1]) : "r"(a))

// ======================= pack X into A-fragment order (tf32-rounded) =======================
__global__ void __launch_bounds__(256) pack_x(const float* __restrict__ src) {
    const uint32_t tid4 = blockIdx.x * 256 + threadIdx.x;   // float4 index
    const uint32_t tile = tid4 >> 9;         // 512 float4 per 128x16 tile
    const uint32_t within = tid4 & 511;
    const uint32_t sub = within >> 5;        // mb*2+ks (0..15)
    const uint32_t lane = within & 31;
    const uint32_t mt = tile >> 8, kt = tile & 255;
    const uint32_t mb = sub >> 1, ks = sub & 1;
    const uint32_t g = lane >> 2, tc = lane & 3;
    const uint32_t r0 = mt * 128 + mb * 16 + g;
    const uint32_t c0 = kt * 16 + ks * 8 + tc;
    const float* p = src + (size_t)r0 * HID + c0;
    float4 o;
    o.x = rna_tf32(p[0]);
    o.y = rna_tf32(p[(size_t)8 * HID]);
    o.z = rna_tf32(p[4]);
    o.w = rna_tf32(p[(size_t)8 * HID + 4]);
    g_Xp[tid4] = o;
}

// ======================= pack W into B-fragment order (tf32-rounded) =======================
__global__ void __launch_bounds__(256) pack_w(const float* __restrict__ src) {
    const uint32_t tid2 = blockIdx.x * 256 + threadIdx.x;   // float2 index
    const uint32_t tile = tid2 >> 11;        // 2048 float2 per 256x16 tile
    const uint32_t within = tid2 & 2047;
    const uint32_t sub = within >> 5;        // nb*2+ks (0..63)
    const uint32_t lane = within & 31;
    const uint32_t nt = tile >> 8, kt = tile & 255;
    const uint32_t nb = sub >> 1, ks = sub & 1;
    const uint32_t g = lane >> 2, tc = lane & 3;
    const uint32_t n = nt * 256 + nb * 8 + g;
    const uint32_t c = kt * 16 + ks * 8 + tc;
    const float* p = src + (size_t)n * HID + c;
    float2 o;
    o.x = rna_tf32(p[0]);
    o.y = rna_tf32(p[4]);
    g_Wp[tid2] = o;
}

// ======================= routing (fp32-exact) + z =======================
__global__ __launch_bounds__(128) void route_kernel(
    const float* __restrict__ x, const float* __restrict__ gate_w,
    const float* __restrict__ bias, const float* __restrict__ lora_A)
{
    const int warp = threadIdx.x >> 5;
    const int lane = threadIdx.x & 31;
    const int n = blockIdx.x * 4 + warp;
    const float* xr = x + (size_t)n * HID;

    float a0 = 0.f, a1 = 0.f, a2 = 0.f, a3 = 0.f;
#pragma unroll 4
    for (int it = 0; it < HID / 128; ++it) {
        int h = (it * 32 + lane) * 4;
        float4 xv = *reinterpret_cast<const float4*>(xr + h);
        a0 += dot4(xv, *reinterpret_cast<const float4*>(gate_w + 0 * HID + h));
        a1 += dot4(xv, *reinterpret_cast<const float4*>(gate_w + 1 * HID + h));
        a2 += dot4(xv, *reinterpret_cast<const float4*>(gate_w + 2 * HID + h));
        a3 += dot4(xv, *reinterpret_cast<const float4*>(gate_w + 3 * HID + h));
    }
    a0 = warp_sum(a0) + bias[0];
    a1 = warp_sum(a1) + bias[1];
    a2 = warp_sum(a2) + bias[2];
    a3 = warp_sum(a3) + bias[3];
    int best = 0; float bv = a0;
    if (a1 > bv) { bv = a1; best = 1; }
    if (a2 > bv) { bv = a2; best = 2; }
    if (a3 > bv) { bv = a3; best = 3; }

    const float* Ab = lora_A + (size_t)best * RANK * HID;
    float z[RANK];
#pragma unroll
    for (int r = 0; r < RANK; ++r) z[r] = 0.f;
#pragma unroll 2
    for (int it = 0; it < HID / 128; ++it) {
        int h = (it * 32 + lane) * 4;
        float4 xv = *reinterpret_cast<const float4*>(xr + h);
#pragma unroll
        for (int r = 0; r < RANK; ++r)
            z[r] += dot4(xv, *reinterpret_cast<const float4*>(Ab + r * HID + h));
    }
#pragma unroll
    for (int r = 0; r < RANK; ++r) z[r] = warp_sum(z[r]);
    if (lane == 0) {
        g_e[n] = best;
#pragma unroll
        for (int r = 0; r < RANK; ++r) g_z[(size_t)n * RANK + r] = z[r];  /* SCALE = 1 */
    }
}

// ======================= GEMM: tf32 mma.sync, 128x256 block, 64x64 warp tile =======================
__global__ void __launch_bounds__(256, 1) gemm_lora(
    const float* __restrict__ loraB, float* __restrict__ out)
{
    extern __shared__ char sm[];
    const uint32_t sbase = smem_u32(sm);

    const int tid = threadIdx.x;
    const int wid = tid >> 5, lane = tid & 31;
    const int wm = wid & 1, wn = wid >> 1;           // 2 x 4 warps
    const int g = lane >> 2, tc = lane & 3;
    const int mt = blockIdx.y, nt = blockIdx.x;
    const int m0 = mt * BM, n0 = nt * BN;

    float acc[4][8][4];
#pragma unroll
    for (int i = 0; i < 4; ++i)
#pragma unroll
        for (int j = 0; j < 8; ++j)
#pragma unroll
            for (int k = 0; k < 4; ++k) acc[i][j][k] = 0.f;

    const char* Abase = reinterpret_cast<const char*>(g_Xp + (size_t)mt * 256 * 512);
    const char* Bbase = reinterpret_cast<const char*>(g_Wp + (size_t)nt * 256 * 2048);

    // ---- stage loader: 12 x cp.async(16B) per thread, fully linear ----
#define LOAD_STAGE(kt2, slot) do {                                            \
    const uint32_t sdst = sbase + (uint32_t)(slot) * STAGE;                   \
    _Pragma("unroll")                                                         \
    for (int q = 0; q < 12; ++q) {                                            \
        const int i = q * 256 + tid;                                          \
        if (i < 1024) {                                                       \
            CP_ASYNC16(sdst + (uint32_t)i * 16,                               \
                       Abase + (size_t)(kt2) * A_STAGE + (size_t)i * 16);     \
        } else {                                                              \
            const int j = i - 1024;                                           \
            CP_ASYNC16(sdst + A_STAGE + (uint32_t)j * 16,                     \
                       Bbase + (size_t)(kt2) * B_STAGE + (size_t)j * 16);     \
        }                                                                     \
    }                                                                         \
    CP_COMMIT();                                                              \
} while (0)

    LOAD_STAGE(0, 0);
    LOAD_STAGE(1, 1);

    // per-warp fragment base addresses (byte offsets within a stage)
    // A(mi,ks2): (ks2>>1)*8192 + (((wm*4+mi)*2 + (ks2&1))*32 + lane)*16
    // B(nj,ks2): A_STAGE + (ks2>>1)*16384 + (((wn*8+nj)*2 + (ks2&1))*32 + lane)*8
    const uint32_t aw = sbase + (uint32_t)((wm * 4) * 2 * 32 + lane) * 16;
    const uint32_t bw = sbase + A_STAGE + (uint32_t)((wn * 8) * 2 * 32 + lane) * 8;

    for (int kt2 = 0; kt2 < NKI; ++kt2) {
        if (kt2 == NKI - 1) { CP_WAIT0(); } else { CP_WAIT1(); }
        __syncthreads();

        const uint32_t soff = (uint32_t)(kt2 % NSTAGE) * STAGE;
#pragma unroll
        for (int ks2 = 0; ks2 < 4; ++ks2) {
            const uint32_t ha = aw + soff + (uint32_t)(ks2 >> 1) * 8192 + (uint32_t)(ks2 & 1) * 512;
            const uint32_t hb = bw + soff + (uint32_t)(ks2 >> 1) * 16384 + (uint32_t)(ks2 & 1) * 256;
            unsigned af[4][4], bf[8][2];
#pragma unroll
            for (int mi = 0; mi < 4; ++mi)
                LDS128(af[mi], ha + (uint32_t)mi * 1024);
#pragma unroll
            for (int nj = 0; nj < 8; ++nj)
                LDS64(bf[nj], hb + (uint32_t)nj * 512);
#pragma unroll
            for (int mi = 0; mi < 4; ++mi)
#pragma unroll
                for (int nj = 0; nj < 8; ++nj)
                    mma8(acc[mi][nj], af[mi], bf[nj]);
        }
        __syncthreads();

        if (kt2 + 2 < NKI) LOAD_STAGE(kt2 + 2, (kt2 + 2) % NSTAGE);
    }
    __syncthreads();

    // ---------------- epilogue: fused LoRA ----------------
    // smem reuse: zs[128*8] @0, es[128] @4096B, Bl[4][256][8] @8192B
    float* zs = reinterpret_cast<float*>(sm);
    int*   es = reinterpret_cast<int*>(sm + 4096);
    float* Bl = reinterpret_cast<float*>(sm + 8192);
    {
        reinterpret_cast<float4*>(zs)[tid] =
            reinterpret_cast<const float4*>(g_z + (size_t)m0 * RANK)[tid];
        if (tid < BM) es[tid] = g_e[m0 + tid];
#pragma unroll
        for (int q = 0; q < 8; ++q) {
            const int i = q * 256 + tid;          // 2048 float4
            const int e = i >> 9, j = i & 511;
            reinterpret_cast<float4*>(Bl)[i] =
                reinterpret_cast<const float4*>(loraB + ((size_t)e * HID + n0) * RANK)[j];
        }
    }
    __syncthreads();

#pragma unroll
    for (int mi = 0; mi < 4; ++mi) {
#pragma unroll
        for (int rp = 0; rp < 2; ++rp) {
            const int row = wm * 64 + mi * 16 + rp * 8 + g;
            const int e = es[row];
            const float4 za = *reinterpret_cast<const float4*>(zs + row * 8);
            const float4 zb = *reinterpret_cast<const float4*>(zs + row * 8 + 4);
            const float* Be = Bl + e * 2048;
            float* orow = out + (size_t)(m0 + row) * HID + n0;
#pragma unroll
            for (int nj = 0; nj < 8; ++nj) {
                const int cl = wn * 64 + nj * 8 + tc * 2;
                float v[2];
#pragma unroll
                for (int cc = 0; cc < 2; ++cc) {
                    const float4 bA = *reinterpret_cast<const float4*>(Be + (cl + cc) * 8);
                    const float4 bB = *reinterpret_cast<const float4*>(Be + (cl + cc) * 8 + 4);
                    v[cc] = acc[mi][nj][rp * 2 + cc] + dot4(za, bA) + dot4(zb, bB);
                }
                float2 st; st.x = v[0]; st.y = v[1];
                *reinterpret_cast<float2*>(orow + cl) = st;
            }
        }
    }
}

// ---------------------------------------------------------------------------
extern "C" void kernel_launch(void* const* d_in, const int* in_sizes, int n_in,
                              void* d_out, int out_size)
{
    const float* x    = (const float*)d_in[0];
    const float* W    = (const float*)d_in[1];
    const float* gate = (const float*)d_in[2];
    const float* bias = (const float*)d_in[3];
    const float* lA   = (const float*)d_in[4];
    const float* lB   = (const float*)d_in[5];
    float* out = (float*)d_out;
    (void)in_sizes; (void)n_in; (void)out_size;

    cudaFuncSetAttribute(gemm_lora, cudaFuncAttributeMaxDynamicSharedMemorySize, SMEM_DYN);

    pack_x<<<(NTOK * (HID / 4)) / 256, 256>>>(x);          // 65536 blocks
    pack_w<<<(HID * (HID / 2)) / 256, 256>>>(W);           // 32768 blocks
    route_kernel<<<NTOK / 4, 128>>>(x, gate, bias, lA);
    dim3 grid(HID / BN, NTOK / BM);                        // (16, 128)
    gemm_lora<<<grid, 256, SMEM_DYN>>>(lB, out);
}